// round 3
// baseline (speedup 1.0000x reference)
#include <cuda_runtime.h>
#include <cstdint>
#include <math.h>

// ---------------------------------------------------------------------------
// B=32, P=1024, HID=512, H=8, D=64, MEM=64, RANK=64
// coeffs[b,p,q] = sum_{i<16} F[b,p,i]*Hh[b,q,i] + Hh[b,q,16]
// ---------------------------------------------------------------------------

#define Bx 32
#define Pn 1024
#define Hn 8

__device__ float g_A[Hn * 64];
__device__ float g_G[17 * 17];
__device__ float g_S1[Bx * Hn];
__device__ float g_S2[Bx * Hn];
__device__ float g_xmm[Bx * 2];
__device__ float g_F[(size_t)Bx * 16 * Pn];   // [b][i][p]
__device__ float g_Hh[(size_t)Bx * 17 * Pn];  // [b][i][p]

// ---------------------------------------------------------------------------
// Kernel 1: fused per-batch min/max (blocks 0..31) + weight prep (block 32)
// ---------------------------------------------------------------------------
__global__ void __launch_bounds__(256) kPrep0(
    const float* __restrict__ x,
    const float* __restrict__ w_k, const float* __restrict__ w_mem,
    const float* __restrict__ w_u, const float* __restrict__ b_u,
    const float* __restrict__ w_v2, const float* __restrict__ b_v2,
    const float* __restrict__ w_v, const float* __restrict__ b_v)
{
    __shared__ float sWU[64][17];
    __shared__ float sWV[64][17];
    int tid = threadIdx.x;

    if (blockIdx.x < 32) {
        // ---- per-batch min/max of x ----
        int b = blockIdx.x;
        float mx = -INFINITY, mn = INFINITY;
        for (int p = tid; p < Pn; p += 256) {
            float v = x[b * Pn + p];
            mx = fmaxf(mx, v); mn = fminf(mn, v);
        }
        #pragma unroll
        for (int off = 16; off; off >>= 1) {
            mx = fmaxf(mx, __shfl_down_sync(0xffffffffu, mx, off));
            mn = fminf(mn, __shfl_down_sync(0xffffffffu, mn, off));
        }
        __shared__ float smx[8], smn[8];
        if ((tid & 31) == 0) { smx[tid >> 5] = mx; smn[tid >> 5] = mn; }
        __syncthreads();
        if (tid == 0) {
            float Mx = smx[0], Mn = smn[0];
            #pragma unroll
            for (int i = 1; i < 8; i++) { Mx = fmaxf(Mx, smx[i]); Mn = fminf(Mn, smn[i]); }
            g_xmm[b * 2 + 0] = Mx;
            g_xmm[b * 2 + 1] = Mn;
        }
        return;
    }

    // ---- weight prep ----
    // A[h][m] = sum_d w_k[h*64+d]*w_mem[m*64+d]
    for (int idx = tid; idx < 512; idx += 256) {
        int h = idx >> 6, m = idx & 63;
        float s = 0.f;
        #pragma unroll 8
        for (int d = 0; d < 64; d++)
            s = fmaf(w_k[h * 64 + d], w_mem[m * 64 + d], s);
        g_A[idx] = s;
    }

    for (int idx = tid; idx < 64 * 16; idx += 256) {
        int r = idx >> 4, i = idx & 15, h = i & 7;
        const float* col = (i < 8) ? w_v : b_v;
        float su = 0.f, sv = 0.f;
        #pragma unroll 8
        for (int d = 0; d < 64; d++) {
            float c = col[h * 64 + d];
            su = fmaf(w_u[r * 512 + h * 64 + d], c, su);
            sv = fmaf(w_v2[r * 512 + h * 64 + d], c, sv);
        }
        sWU[r][i] = su;
        sWV[r][i] = sv;
    }
    if (tid < 64) { sWU[tid][16] = b_u[tid]; sWV[tid][16] = b_v2[tid]; }
    __syncthreads();

    for (int idx = tid; idx < 289; idx += 256) {
        int i = idx / 17, j = idx % 17;
        float s = 0.f;
        #pragma unroll 8
        for (int r = 0; r < 64; r++)
            s = fmaf(sWU[r][i], sWV[r][j], s);
        g_G[idx] = s;
    }
}

// ---------------------------------------------------------------------------
// Kernel 2: softmax statistics S1[b,h], S2[b,h]
// ---------------------------------------------------------------------------
__global__ void __launch_bounds__(512) kStats(const float* __restrict__ x)
{
    int h = blockIdx.x, b = blockIdx.y;
    __shared__ float sx[Pn];
    __shared__ float sT[64];
    int tid = threadIdx.x;
    sx[tid] = x[b * Pn + tid];
    sx[tid + 512] = x[b * Pn + tid + 512];
    __syncthreads();

    int m = tid >> 3, sub = tid & 7;
    float a = g_A[h * 64 + m];
    float sh = (a >= 0.f) ? a * g_xmm[b * 2 + 0] : a * g_xmm[b * 2 + 1];
    float num = 0.f, den = 0.f;
    #pragma unroll 4
    for (int p = sub; p < Pn; p += 8) {
        float xv = sx[p];
        float e = __expf(fmaf(a, xv, -sh));
        den += e;
        num = fmaf(xv, e, num);
    }
    #pragma unroll
    for (int off = 4; off; off >>= 1) {
        num += __shfl_down_sync(0xffffffffu, num, off, 8);
        den += __shfl_down_sync(0xffffffffu, den, off, 8);
    }
    if (sub == 0) sT[m] = num / den;
    __syncthreads();
    if (tid < 32) {
        float t0 = sT[tid], t1 = sT[tid + 32];
        float s1 = t0 + t1;
        float s2 = fmaf(t0, t0, t1 * t1);
        #pragma unroll
        for (int off = 16; off; off >>= 1) {
            s1 += __shfl_down_sync(0xffffffffu, s1, off);
            s2 += __shfl_down_sync(0xffffffffu, s2, off);
        }
        if (tid == 0) { g_S1[b * Hn + h] = s1; g_S2[b * Hn + h] = s2; }
    }
}

// ---------------------------------------------------------------------------
// Kernel 3: features. 256 threads, thread = (p_local, h). 32 p per block.
// ---------------------------------------------------------------------------
__global__ void __launch_bounds__(256) kFeat(
    const float* __restrict__ x,
    const float* __restrict__ w_q, const float* __restrict__ b_q,
    const float* __restrict__ w_v, const float* __restrict__ b_v)
{
    __shared__ float swq[512], sbq[512], swv[512], sbv[512];
    __shared__ float sG[289];
    __shared__ float sS1[8], sS2[8];
    __shared__ float sF[17][32];
    __shared__ float sxv[32];

    int b = blockIdx.y, tid = threadIdx.x;
    int p0 = blockIdx.x * 32;

    for (int i = tid; i < 512; i += 256) {
        swq[i] = w_q[i]; sbq[i] = b_q[i];
        swv[i] = w_v[i]; sbv[i] = b_v[i];
    }
    for (int i = tid; i < 289; i += 256) sG[i] = g_G[i];
    if (tid < 8) { sS1[tid] = g_S1[b * Hn + tid]; sS2[tid] = g_S2[b * Hn + tid]; }
    if (tid < 32) sxv[tid] = x[b * Pn + p0 + tid];
    __syncthreads();

    int h = tid >> 5, pl = tid & 31;
    float xv = sxv[pl];
    const float4* wq4 = (const float4*)&swq[h * 64];
    const float4* bq4 = (const float4*)&sbq[h * 64];
    const float4* wv4 = (const float4*)&swv[h * 64];
    const float4* bv4 = (const float4*)&sbv[h * 64];

    float a1 = 0.f, a2 = 0.f;
    #pragma unroll
    for (int d4 = 0; d4 < 16; d4++) {
        float4 q = wq4[d4], bq = bq4[d4], wv = wv4[d4], bv = bv4[d4];
        float v, qf;
        v = fmaf(xv, q.x, bq.x); qf = (v > 0.f) ? (v + 1.f) : __expf(v);
        a1 = fmaf(qf, wv.x, a1); a2 = fmaf(qf, bv.x, a2);
        v = fmaf(xv, q.y, bq.y); qf = (v > 0.f) ? (v + 1.f) : __expf(v);
        a1 = fmaf(qf, wv.y, a1); a2 = fmaf(qf, bv.y, a2);
        v = fmaf(xv, q.z, bq.z); qf = (v > 0.f) ? (v + 1.f) : __expf(v);
        a1 = fmaf(qf, wv.z, a1); a2 = fmaf(qf, bv.z, a2);
        v = fmaf(xv, q.w, bq.w); qf = (v > 0.f) ? (v + 1.f) : __expf(v);
        a1 = fmaf(qf, wv.w, a1); a2 = fmaf(qf, bv.w, a2);
    }
    float s1 = sS1[h], s2 = sS2[h];
    sF[h][pl]     = fmaf(a1, s2, a2 * s1);   // alpha
    sF[8 + h][pl] = fmaf(a1, s1, 64.f * a2); // beta
    if (h == 0) sF[16][pl] = 1.f;
    __syncthreads();

    // write F [16 x 32]
    size_t baseF = ((size_t)b * 16) * Pn + p0;
    #pragma unroll
    for (int rep = 0; rep < 2; rep++) {
        int idx = tid + rep * 256;
        int i = idx >> 5, pl2 = idx & 31;
        g_F[baseF + (size_t)i * Pn + pl2] = sF[i][pl2];
    }

    // Hh [17 x 32]
    size_t baseH = ((size_t)b * 17) * Pn + p0;
    for (int o = tid; o < 544; o += 256) {
        int i = o >> 5, pl2 = o & 31;
        float s = 0.f;
        #pragma unroll
        for (int j = 0; j < 17; j++)
            s = fmaf(sG[i * 17 + j], sF[j][pl2], s);
        g_Hh[baseH + (size_t)i * Pn + pl2] = s;
    }
}

// ---------------------------------------------------------------------------
// Kernel 4: bilinear GEMM, 128x128 tile, 512 threads, 4x8 microtile, FFMA2.
// A is stored pre-duplicated in shared so both FFMA2 operands come straight
// from LDS.128 register pairs (no per-k MOVs).
// ---------------------------------------------------------------------------
#define PACK2(out64, lo, hi) \
    asm("mov.b64 %0, {%1, %2};" : "=l"(out64) : "r"(__float_as_uint(lo)), "r"(__float_as_uint(hi)))
#define FMA2(acc64, a64, b64) \
    asm("fma.rn.f32x2 %0, %1, %2, %0;" : "+l"(acc64) : "l"(a64), "l"(b64))
#define UNPACK2(lo, hi, in64) do { \
    unsigned _u0, _u1; \
    asm("mov.b64 {%0, %1}, %2;" : "=r"(_u0), "=r"(_u1) : "l"(in64)); \
    lo = __uint_as_float(_u0); hi = __uint_as_float(_u1); } while (0)

__global__ void __launch_bounds__(512) kGemm(float* __restrict__ out)
{
    const int b = blockIdx.z;
    const int tq0 = blockIdx.x * 128;
    const int tp0 = blockIdx.y * 128;

    __shared__ float sA2[16][256];   // F tile, each value duplicated (pairs)
    __shared__ float sB[16][128];    // Hh tile
    __shared__ float sH16[128];      // bias row

    const int tid = threadIdx.x;
    const float* Fb = g_F + ((size_t)b * 16) * Pn;
    const float* Hb = g_Hh + ((size_t)b * 17) * Pn;

    {
        int row = tid >> 5, c4 = (tid & 31) << 2;
        // B tile: 512 float4
        *(float4*)&sB[row][c4] = *(const float4*)&Hb[(size_t)row * Pn + tq0 + c4];
        // A tile duplicated
        float4 v = *(const float4*)&Fb[(size_t)row * Pn + tp0 + c4];
        *(float4*)&sA2[row][c4 * 2]     = make_float4(v.x, v.x, v.y, v.y);
        *(float4*)&sA2[row][c4 * 2 + 4] = make_float4(v.z, v.z, v.w, v.w);
    }
    if (tid < 32)
        *(float4*)&sH16[tid * 4] = *(const float4*)&Hb[(size_t)16 * Pn + tq0 + tid * 4];
    __syncthreads();

    const int tx = tid & 15, ty = tid >> 4;
    const int c0 = tx * 8;          // 8 cols
    const int r0 = ty * 4;          // 4 rows

    unsigned long long acc[4][4];
    {
        float4 h0 = *(const float4*)&sH16[c0];
        float4 h1 = *(const float4*)&sH16[c0 + 4];
        unsigned long long hp0, hp1, hp2, hp3;
        PACK2(hp0, h0.x, h0.y); PACK2(hp1, h0.z, h0.w);
        PACK2(hp2, h1.x, h1.y); PACK2(hp3, h1.z, h1.w);
        #pragma unroll
        for (int r = 0; r < 4; r++) {
            acc[r][0] = hp0; acc[r][1] = hp1; acc[r][2] = hp2; acc[r][3] = hp3;
        }
    }

    #pragma unroll
    for (int k = 0; k < 16; k++) {
        float4 ad0 = *(const float4*)&sA2[k][r0 * 2];       // (a0,a0,a1,a1)
        float4 ad1 = *(const float4*)&sA2[k][r0 * 2 + 4];   // (a2,a2,a3,a3)
        float4 b0  = *(const float4*)&sB[k][c0];
        float4 b1  = *(const float4*)&sB[k][c0 + 4];
        unsigned long long ap[4], bp[4];
        PACK2(ap[0], ad0.x, ad0.y); PACK2(ap[1], ad0.z, ad0.w);
        PACK2(ap[2], ad1.x, ad1.y); PACK2(ap[3], ad1.z, ad1.w);
        PACK2(bp[0], b0.x, b0.y);   PACK2(bp[1], b0.z, b0.w);
        PACK2(bp[2], b1.x, b1.y);   PACK2(bp[3], b1.z, b1.w);
        #pragma unroll
        for (int r = 0; r < 4; r++) {
            FMA2(acc[r][0], ap[r], bp[0]);
            FMA2(acc[r][1], ap[r], bp[1]);
            FMA2(acc[r][2], ap[r], bp[2]);
            FMA2(acc[r][3], ap[r], bp[3]);
        }
    }

    float* outb = out + (size_t)b * Pn * Pn;
    #pragma unroll
    for (int r = 0; r < 4; r++) {
        float* rowp = outb + (size_t)(tp0 + r0 + r) * Pn + tq0;
        float4 v0, v1;
        UNPACK2(v0.x, v0.y, acc[r][0]);
        UNPACK2(v0.z, v0.w, acc[r][1]);
        UNPACK2(v1.x, v1.y, acc[r][2]);
        UNPACK2(v1.z, v1.w, acc[r][3]);
        *(float4*)&rowp[c0]     = v0;
        *(float4*)&rowp[c0 + 4] = v1;
    }
}

// ---------------------------------------------------------------------------
// inputs: 0 x, 1 w_q, 2 b_q, 3 w_k, 4 b_k(unused), 5 w_v, 6 b_v, 7 w_mem,
//         8 w_u, 9 b_u, 10 w_v2, 11 b_v2
// ---------------------------------------------------------------------------
extern "C" void kernel_launch(void* const* d_in, const int* in_sizes, int n_in,
                              void* d_out, int out_size)
{
    const float* x    = (const float*)d_in[0];
    const float* w_q  = (const float*)d_in[1];
    const float* b_q  = (const float*)d_in[2];
    const float* w_k  = (const float*)d_in[3];
    const float* w_v  = (const float*)d_in[5];
    const float* b_v  = (const float*)d_in[6];
    const float* w_mem = (const float*)d_in[7];
    const float* w_u  = (const float*)d_in[8];
    const float* b_u  = (const float*)d_in[9];
    const float* w_v2 = (const float*)d_in[10];
    const float* b_v2 = (const float*)d_in[11];
    float* out = (float*)d_out;

    kPrep0<<<33, 256>>>(x, w_k, w_mem, w_u, b_u, w_v2, b_v2, w_v, b_v);
    kStats<<<dim3(Hn, Bx), 512>>>(x);
    kFeat<<<dim3(Pn / 32, Bx), 256>>>(x, w_q, b_q, w_v, b_v);
    kGemm<<<dim3(Pn / 128, Pn / 128, Bx), 512>>>(out);
}

// round 5
// speedup vs baseline: 1.4496x; 1.4496x over previous
#include <cuda_runtime.h>
#include <cstdint>
#include <math.h>

// ---------------------------------------------------------------------------
// B=32, P=1024, HID=512, H=8, D=64, MEM=64, RANK=64
// coeffs[b,p,q] = sum_{i<16} F[b,p,i]*Hh[b,q,i] + Hh[b,q,16]
// ---------------------------------------------------------------------------

#define Bx 32
#define Pn 1024
#define Hn 8

__device__ float g_G[17 * 17];
__device__ float g_S1[Bx * Hn];
__device__ float g_S2[Bx * Hn];
__device__ float g_F[(size_t)Bx * 16 * Pn];   // [b][i][p]
__device__ float g_Hh[(size_t)Bx * 17 * Pn];  // [b][i][p]

// ---------------------------------------------------------------------------
// Kernel 1: per-(b,h) softmax stats, self-contained (minmax + A column local).
// Block (0,0) additionally computes the 17x17 bilinear form G.
// grid (Hn, Bx), 512 threads.
// ---------------------------------------------------------------------------
__global__ void __launch_bounds__(512) kStats(
    const float* __restrict__ x,
    const float* __restrict__ w_k, const float* __restrict__ w_mem,
    const float* __restrict__ w_u, const float* __restrict__ b_u,
    const float* __restrict__ w_v2, const float* __restrict__ b_v2,
    const float* __restrict__ w_v, const float* __restrict__ b_v)
{
    __shared__ float sx[Pn];
    __shared__ float sT[64];
    __shared__ float sred[32];
    __shared__ float sMx, sMn;
    __shared__ float sWU[64][17];
    __shared__ float sWV[64][17];

    const int h = blockIdx.x, b = blockIdx.y;
    const int tid = threadIdx.x;
    const int lane = tid & 31, wid = tid >> 5;

    float x0 = x[b * Pn + tid], x1 = x[b * Pn + tid + 512];
    sx[tid] = x0; sx[tid + 512] = x1;

    // block min/max
    float mx = fmaxf(x0, x1), mn = fminf(x0, x1);
    #pragma unroll
    for (int off = 16; off; off >>= 1) {
        mx = fmaxf(mx, __shfl_down_sync(0xffffffffu, mx, off));
        mn = fminf(mn, __shfl_down_sync(0xffffffffu, mn, off));
    }
    if (lane == 0) { sred[wid] = mx; sred[16 + wid] = mn; }
    __syncthreads();
    if (tid == 0) {
        float M = sred[0];
        #pragma unroll
        for (int i = 1; i < 16; i++) M = fmaxf(M, sred[i]);
        sMx = M;
        float m2 = sred[16];
        #pragma unroll
        for (int i = 1; i < 16; i++) m2 = fminf(m2, sred[16 + i]);
        sMn = m2;
    }

    // A[h][m] for this block's h: 8 threads per m
    const int m = tid >> 3, sub = tid & 7;
    float a = 0.f;
    #pragma unroll
    for (int j = 0; j < 8; j++)
        a = fmaf(w_k[h * 64 + sub + 8 * j], w_mem[m * 64 + sub + 8 * j], a);
    a += __shfl_xor_sync(0xffffffffu, a, 1);
    a += __shfl_xor_sync(0xffffffffu, a, 2);
    a += __shfl_xor_sync(0xffffffffu, a, 4);
    __syncthreads();

    const float sh = (a >= 0.f) ? a * sMx : a * sMn;
    float num = 0.f, den = 0.f;
    #pragma unroll 4
    for (int p = sub; p < Pn; p += 8) {
        float xv = sx[p];
        float e = __expf(fmaf(a, xv, -sh));
        den += e;
        num = fmaf(xv, e, num);
    }
    #pragma unroll
    for (int off = 4; off; off >>= 1) {
        num += __shfl_down_sync(0xffffffffu, num, off, 8);
        den += __shfl_down_sync(0xffffffffu, den, off, 8);
    }
    if (sub == 0) sT[m] = num / den;
    __syncthreads();
    if (tid < 32) {
        float t0 = sT[tid], t1 = sT[tid + 32];
        float s1 = t0 + t1;
        float s2 = fmaf(t0, t0, t1 * t1);
        #pragma unroll
        for (int off = 16; off; off >>= 1) {
            s1 += __shfl_down_sync(0xffffffffu, s1, off);
            s2 += __shfl_down_sync(0xffffffffu, s2, off);
        }
        if (tid == 0) { g_S1[b * Hn + h] = s1; g_S2[b * Hn + h] = s2; }
    }

    // G on block (0,0) only
    if (h == 0 && b == 0) {
        for (int idx = tid; idx < 64 * 16; idx += 512) {
            int r = idx >> 4, i = idx & 15, hh = i & 7;
            const float* col = (i < 8) ? w_v : b_v;
            float su = 0.f, sv = 0.f;
            #pragma unroll 8
            for (int d = 0; d < 64; d++) {
                float c = col[hh * 64 + d];
                su = fmaf(w_u[r * 512 + hh * 64 + d], c, su);
                sv = fmaf(w_v2[r * 512 + hh * 64 + d], c, sv);
            }
            sWU[r][i] = su;
            sWV[r][i] = sv;
        }
        if (tid < 64) { sWU[tid][16] = b_u[tid]; sWV[tid][16] = b_v2[tid]; }
        __syncthreads();
        for (int idx = tid; idx < 289; idx += 512) {
            int i = idx / 17, j = idx % 17;
            float s = 0.f;
            #pragma unroll 8
            for (int r = 0; r < 64; r++)
                s = fmaf(sWU[r][i], sWV[r][j], s);
            g_G[idx] = s;
        }
    }
}

// ---------------------------------------------------------------------------
// Kernel 2: features. 512 threads, thread = (h, p_local), 64 p per block.
// grid (Pn/64, Bx).
// ---------------------------------------------------------------------------
__global__ void __launch_bounds__(512) kFeat(
    const float* __restrict__ x,
    const float* __restrict__ w_q, const float* __restrict__ b_q,
    const float* __restrict__ w_v, const float* __restrict__ b_v)
{
    __shared__ float swq[512], sbq[512], swv[512], sbv[512];
    __shared__ float sG[289];
    __shared__ float sS1[8], sS2[8];
    __shared__ float sF[17][64];
    __shared__ float sxv[64];

    const int b = blockIdx.y, tid = threadIdx.x;
    const int p0 = blockIdx.x * 64;

    swq[tid] = w_q[tid]; sbq[tid] = b_q[tid];
    swv[tid] = w_v[tid]; sbv[tid] = b_v[tid];
    if (tid < 289) sG[tid] = g_G[tid];
    if (tid < 8) { sS1[tid] = g_S1[b * Hn + tid]; sS2[tid] = g_S2[b * Hn + tid]; }
    if (tid < 64) sxv[tid] = x[b * Pn + p0 + tid];
    __syncthreads();

    const int h = tid >> 6, pl = tid & 63;
    const float xv = sxv[pl];
    const float4* wq4 = (const float4*)&swq[h * 64];
    const float4* bq4 = (const float4*)&sbq[h * 64];
    const float4* wv4 = (const float4*)&swv[h * 64];
    const float4* bv4 = (const float4*)&sbv[h * 64];

    float a1 = 0.f, a2 = 0.f;
    #pragma unroll
    for (int d4 = 0; d4 < 16; d4++) {
        float4 q = wq4[d4], bq = bq4[d4], wv = wv4[d4], bv = bv4[d4];
        float v, qf;
        v = fmaf(xv, q.x, bq.x); qf = (v > 0.f) ? (v + 1.f) : __expf(v);
        a1 = fmaf(qf, wv.x, a1); a2 = fmaf(qf, bv.x, a2);
        v = fmaf(xv, q.y, bq.y); qf = (v > 0.f) ? (v + 1.f) : __expf(v);
        a1 = fmaf(qf, wv.y, a1); a2 = fmaf(qf, bv.y, a2);
        v = fmaf(xv, q.z, bq.z); qf = (v > 0.f) ? (v + 1.f) : __expf(v);
        a1 = fmaf(qf, wv.z, a1); a2 = fmaf(qf, bv.z, a2);
        v = fmaf(xv, q.w, bq.w); qf = (v > 0.f) ? (v + 1.f) : __expf(v);
        a1 = fmaf(qf, wv.w, a1); a2 = fmaf(qf, bv.w, a2);
    }
    const float s1 = sS1[h], s2 = sS2[h];
    sF[h][pl]     = fmaf(a1, s2, a2 * s1);   // alpha
    sF[8 + h][pl] = fmaf(a1, s1, 64.f * a2); // beta
    if (h == 0) sF[16][pl] = 1.f;
    __syncthreads();

    // F [16 x 64]
    {
        size_t baseF = ((size_t)b * 16) * Pn + p0;
        int i = tid >> 6, pl2 = tid & 63;
        g_F[baseF + (size_t)i * Pn + pl2] = sF[i][pl2];
        g_F[baseF + (size_t)(i + 8) * Pn + pl2] = sF[i + 8][pl2];
    }
    // Hh [17 x 64]
    {
        size_t baseH = ((size_t)b * 17) * Pn + p0;
        for (int o = tid; o < 17 * 64; o += 512) {
            int i = o >> 6, pl2 = o & 63;
            float s = 0.f;
            #pragma unroll
            for (int j = 0; j < 17; j++)
                s = fmaf(sG[i * 17 + j], sF[j][pl2], s);
            g_Hh[baseH + (size_t)i * Pn + pl2] = s;
        }
    }
}

// ---------------------------------------------------------------------------
// Kernel 3: bilinear GEMM.
// Block: 256 threads (8 warps), tile 128p x 64q.
// Lane owns a q-pair; Hh (B operand + bias) lives in 17 f32x2 REGISTERS,
// loaded once. A comes from a duplicated F tile via uniform-address
// LDS.128 broadcasts. Inner loop: 16 FFMA2 + 8 broadcast LDS per warp per k
// -> fma-pipe bound.
// ---------------------------------------------------------------------------
#define FMA2(acc64, a64, b64) \
    asm("fma.rn.f32x2 %0, %1, %2, %0;" : "+l"(acc64) : "l"(a64), "l"(b64))
#define UNPACK2(lo, hi, in64) do { \
    unsigned _u0, _u1; \
    asm("mov.b64 {%0, %1}, %2;" : "=r"(_u0), "=r"(_u1) : "l"(in64)); \
    lo = __uint_as_float(_u0); hi = __uint_as_float(_u1); } while (0)

__global__ void __launch_bounds__(256) kGemm(float* __restrict__ out)
{
    const int b = blockIdx.z;
    const int tq0 = blockIdx.x * 64;
    const int tp0 = blockIdx.y * 128;

    __shared__ __align__(16) float sFd[16][256];  // F tile, values duplicated in pairs
    __shared__ __align__(16) float sHh[17][64];   // Hh tile rows 0..15 + bias row 16

    const int tid = threadIdx.x;
    const int lane = tid & 31, w = tid >> 5;
    const float* Fb = g_F + ((size_t)b * 16) * Pn;
    const float* Hb = g_Hh + ((size_t)b * 17) * Pn;

    // load F tile (16 x 128) duplicated -> sFd (16 x 256)
    #pragma unroll
    for (int rep = 0; rep < 2; rep++) {
        int idx = tid + rep * 256;
        int row = idx >> 5, c4 = (idx & 31) << 2;
        float4 v = *(const float4*)&Fb[(size_t)row * Pn + tp0 + c4];
        *(float4*)&sFd[row][c4 * 2]     = make_float4(v.x, v.x, v.y, v.y);
        *(float4*)&sFd[row][c4 * 2 + 4] = make_float4(v.z, v.z, v.w, v.w);
    }
    // load Hh tile (17 x 64) = 272 float4
    {
        int idx = tid;
        int row = idx >> 4, c4 = (idx & 15) << 2;
        *(float4*)&sHh[row][c4] = *(const float4*)&Hb[(size_t)row * Pn + tq0 + c4];
        if (tid < 16) {
            int idx2 = tid + 256;
            int row2 = idx2 >> 4, c42 = (idx2 & 15) << 2;
            *(float4*)&sHh[row2][c42] = *(const float4*)&Hb[(size_t)row2 * Pn + tq0 + c42];
        }
    }
    __syncthreads();

    // B operand: per-lane q-pair for all k, plus bias -> registers
    unsigned long long bq[16];
    #pragma unroll
    for (int k = 0; k < 16; k++)
        bq[k] = *(const unsigned long long*)&sHh[k][2 * lane];
    const unsigned long long hbias = *(const unsigned long long*)&sHh[16][2 * lane];

    unsigned long long acc[16];
    #pragma unroll
    for (int r = 0; r < 16; r++) acc[r] = hbias;

    const int rowbase = w * 16;   // this warp's 16 p rows
    #pragma unroll
    for (int k = 0; k < 16; k++) {
        const float* fr = &sFd[k][rowbase * 2];
        #pragma unroll
        for (int rp = 0; rp < 8; rp++) {
            ulonglong2 ad = *(const ulonglong2*)&fr[rp * 4];  // rows 2rp, 2rp+1 (dup pairs)
            FMA2(acc[2 * rp],     ad.x, bq[k]);
            FMA2(acc[2 * rp + 1], ad.y, bq[k]);
        }
    }

    float* outb = out + (size_t)b * Pn * Pn + (size_t)(tp0 + rowbase) * Pn + tq0 + 2 * lane;
    #pragma unroll
    for (int r = 0; r < 16; r++) {
        float2 v;
        UNPACK2(v.x, v.y, acc[r]);
        *(float2*)&outb[(size_t)r * Pn] = v;
    }
}

// ---------------------------------------------------------------------------
// inputs: 0 x, 1 w_q, 2 b_q, 3 w_k, 4 b_k(unused), 5 w_v, 6 b_v, 7 w_mem,
//         8 w_u, 9 b_u, 10 w_v2, 11 b_v2
// ---------------------------------------------------------------------------
extern "C" void kernel_launch(void* const* d_in, const int* in_sizes, int n_in,
                              void* d_out, int out_size)
{
    const float* x    = (const float*)d_in[0];
    const float* w_q  = (const float*)d_in[1];
    const float* b_q  = (const float*)d_in[2];
    const float* w_k  = (const float*)d_in[3];
    const float* w_v  = (const float*)d_in[5];
    const float* b_v  = (const float*)d_in[6];
    const float* w_mem = (const float*)d_in[7];
    const float* w_u  = (const float*)d_in[8];
    const float* b_u  = (const float*)d_in[9];
    const float* w_v2 = (const float*)d_in[10];
    const float* b_v2 = (const float*)d_in[11];
    float* out = (float*)d_out;

    kStats<<<dim3(Hn, Bx), 512>>>(x, w_k, w_mem, w_u, b_u, w_v2, b_v2, w_v, b_v);
    kFeat<<<dim3(Pn / 64, Bx), 512>>>(x, w_q, b_q, w_v, b_v);
    kGemm<<<dim3(Pn / 64, Pn / 128, Bx), 256>>>(out);
}